// round 2
// baseline (speedup 1.0000x reference)
#include <cuda_runtime.h>

#define HW 4096
#define NB 4

// ---------------- scratch (device globals: no allocations allowed) ----------
__device__ float g_qT[NB * HW * 8];        // [b][s][d]  512 KB
__device__ float g_kT[NB * HW * 8];        // [b][t][d]  512 KB
__device__ float g_xT[NB * HW * 64];       // [b][s][c]  4 MB
__device__ int   g_idx[NB * HW * 9];       // [b][t][9]  576 KB
__device__ float g_Wt[576 * 64];           // [kk*64+c][o] 147 KB

// ---------------- prep: weight transpose (OC,C,9) -> Wt[kk*64+c][o] ---------
__global__ void k_prep_w(const float* __restrict__ W) {
    int j = blockIdx.x * 256 + threadIdx.x;
    if (j >= 576 * 64) return;
    int r = j >> 6, o = j & 63;        // r = kk*64 + c
    int kk = r >> 6, c = r & 63;
    g_Wt[j] = W[o * 576 + c * 9 + kk];
}

// ---------------- k1: 1x1 convs (q,k) + x transpose -------------------------
// grid 128 (B * 4096/128), block 128. Each block: one b, 128 s positions.
__global__ void k_proj(const float* __restrict__ x, const float* __restrict__ qw,
                       const float* __restrict__ qb, const float* __restrict__ kw,
                       const float* __restrict__ kb) {
    __shared__ float tile[64][129];     // padded: conflict-free transpose
    __shared__ float wq[512], wk[512];
    int tid = threadIdx.x;
    int b  = blockIdx.x >> 5;
    int s0 = (blockIdx.x & 31) << 7;

    for (int u = tid; u < 512; u += 128) { wq[u] = qw[u]; wk[u] = kw[u]; }
    for (int u = tid; u < 64 * 128; u += 128) {
        int c = u >> 7, sl = u & 127;
        tile[c][sl] = x[(b * 64 + c) * HW + s0 + sl];   // coalesced
    }
    __syncthreads();

    // coalesced xT write: xT[b][s][c]
    for (int u = tid; u < 128 * 64; u += 128) {
        int sl = u >> 6, c = u & 63;
        g_xT[((size_t)b * HW + s0 + sl) * 64 + c] = tile[c][sl];
    }

    // q,k projection for this thread's s
    float qa[8], ka[8];
    #pragma unroll
    for (int d = 0; d < 8; ++d) { qa[d] = __ldg(qb + d); ka[d] = __ldg(kb + d); }
    int sl = tid;
    #pragma unroll 4
    for (int c = 0; c < 64; ++c) {
        float xv = tile[c][sl];
        #pragma unroll
        for (int d = 0; d < 8; ++d) {
            qa[d] = fmaf(wq[d * 64 + c], xv, qa[d]);
            ka[d] = fmaf(wk[d * 64 + c], xv, ka[d]);
        }
    }
    float4* qT4 = (float4*)g_qT;
    float4* kT4 = (float4*)g_kT;
    int base = (b * HW + s0 + sl) * 2;
    qT4[base]     = make_float4(qa[0], qa[1], qa[2], qa[3]);
    qT4[base + 1] = make_float4(qa[4], qa[5], qa[6], qa[7]);
    kT4[base]     = make_float4(ka[0], ka[1], ka[2], ka[3]);
    kT4[base + 1] = make_float4(ka[4], ka[5], ka[6], ka[7]);
}

// ---------------- k2: fused energy + top-9 ----------------------------------
// grid 256 (B * 4096/64), block 256. 64 t per block, 4 threads per t (strided s).
__global__ void k_topk() {
    __shared__ float4 qs4[1024];              // 512 s x 8 floats (16 KB)
    __shared__ float  mval[64 * 4 * 9];
    __shared__ int    midx[64 * 4 * 9];
    int tid = threadIdx.x;
    int w = tid >> 5, lane = tid & 31;
    int tl = ((w & 1) << 5) | lane;           // 0..63 : local t
    int h  = w >> 1;                          // 0..3  : s-partition
    int b  = blockIdx.x >> 6;
    int t0 = (blockIdx.x & 63) << 6;
    int t  = t0 + tl;

    const float4* kT4 = (const float4*)g_kT;
    float4 kA = kT4[(b * HW + t) * 2];
    float4 kB = kT4[(b * HW + t) * 2 + 1];

    float v[9]; int ix[9];
    #pragma unroll
    for (int j = 0; j < 9; ++j) { v[j] = -3.4e38f; ix[j] = -1; }

    const float4* qbase = ((const float4*)g_qT) + (size_t)b * HW * 2;
    for (int cb = 0; cb < HW; cb += 512) {
        __syncthreads();
        for (int u = tid; u < 1024; u += 256) qs4[u] = qbase[cb * 2 + u];
        __syncthreads();
        #pragma unroll 2
        for (int i = 0; i < 128; ++i) {
            int sl = (i << 2) | h;            // broadcast LDS within warp
            float4 A  = qs4[sl * 2];
            float4 Bq = qs4[sl * 2 + 1];
            float e  = kA.x * A.x;
            e  = fmaf(kA.y, A.y, e);
            e  = fmaf(kA.z, A.z, e);
            e  = fmaf(kA.w, A.w, e);
            float e2 = kB.x * Bq.x;
            e2 = fmaf(kB.y, Bq.y, e2);
            e2 = fmaf(kB.z, Bq.z, e2);
            e2 = fmaf(kB.w, Bq.w, e2);
            e += e2;
            if (e > v[8]) {                   // rare: sorted insert (reg-resident)
                v[8] = e; ix[8] = cb + sl;
                #pragma unroll
                for (int j = 8; j > 0; --j) {
                    if (v[j] > v[j - 1]) {
                        float tv = v[j]; v[j] = v[j - 1]; v[j - 1] = tv;
                        int   ti = ix[j]; ix[j] = ix[j - 1]; ix[j - 1] = ti;
                    }
                }
            }
        }
    }
    int mbase = (tl * 4 + h) * 9;
    #pragma unroll
    for (int j = 0; j < 9; ++j) { mval[mbase + j] = v[j]; midx[mbase + j] = ix[j]; }
    __syncthreads();

    if (h == 0) {
        float mv[9]; int mi[9];
        #pragma unroll
        for (int j = 0; j < 9; ++j) { mv[j] = v[j]; mi[j] = ix[j]; }
        for (int hh = 1; hh < 4; ++hh) {
            int cbs = (tl * 4 + hh) * 9;
            for (int j = 0; j < 9; ++j) {
                float cv = mval[cbs + j]; int ci = midx[cbs + j];
                // (val desc, idx asc): matches jax top_k tie semantics
                if (cv > mv[8] || (cv == mv[8] && ci < mi[8])) {
                    mv[8] = cv; mi[8] = ci;
                    #pragma unroll
                    for (int j2 = 8; j2 > 0; --j2) {
                        bool sw = (mv[j2] > mv[j2 - 1]) ||
                                  (mv[j2] == mv[j2 - 1] && mi[j2] < mi[j2 - 1]);
                        if (sw) {
                            float tv = mv[j2]; mv[j2] = mv[j2 - 1]; mv[j2 - 1] = tv;
                            int   ti = mi[j2]; mi[j2] = mi[j2 - 1]; mi[j2 - 1] = ti;
                        }
                    }
                }
            }
        }
        // sort the 9 indices ascending (reference sorts idx)
        #pragma unroll
        for (int p = 0; p < 8; ++p)
            #pragma unroll
            for (int j = 0; j < 8; ++j)
                if (j < 8 - p && mi[j] > mi[j + 1]) {
                    int ti = mi[j]; mi[j] = mi[j + 1]; mi[j + 1] = ti;
                }
        #pragma unroll
        for (int j = 0; j < 9; ++j)
            g_idx[((size_t)b * HW + t) * 9 + j] = mi[j];
    }
}

// ---------------- k3: gather + 9-tap conv + relu + residual -----------------
// grid 128 persistent blocks, 512 threads. Tile = 32 t. smem: Wt(147K)+g(74K)+idx.
__global__ void k_conv(const float* __restrict__ bias, const float* __restrict__ gamma,
                       float* __restrict__ out) {
    extern __shared__ float sm[];
    float* Wsm  = sm;                         // 36864 floats
    float* gbuf = sm + 36864;                 // 32 rows, stride 580 (pad: no conflicts)
    int*   idxs = (int*)(sm + 36864 + 32 * 580);
    int tid = threadIdx.x;

    for (int u = tid; u < 36864; u += 512) Wsm[u] = g_Wt[u];
    float gamma0 = __ldg(gamma);
    int tt = tid >> 4;                        // 0..31 : local t
    int og = tid & 15;                        // 0..15 : 4 output channels each
    const float4* W4 = (const float4*)Wsm;
    float b0 = __ldg(bias + (og << 2)), b1 = __ldg(bias + (og << 2) + 1);
    float b2 = __ldg(bias + (og << 2) + 2), b3 = __ldg(bias + (og << 2) + 3);

    for (int tile = blockIdx.x; tile < 512; tile += gridDim.x) {
        int b  = tile >> 7;
        int t0 = (tile & 127) << 5;
        __syncthreads();                      // prev compute done reading gbuf
        for (int u = tid; u < 288; u += 512)
            idxs[u] = g_idx[((size_t)b * HW + t0) * 9 + u];
        __syncthreads();
        // gather: 288 rows of 64 contiguous floats from xT
        const float4* xT4 = ((const float4*)g_xT) + (size_t)b * HW * 16;
        float4* g4 = (float4*)gbuf;
        for (int u = tid; u < 4608; u += 512) {
            int ttl = u / 144;
            int vv  = u - ttl * 144;
            int kk  = vv >> 4, cv = vv & 15;
            int pos = idxs[ttl * 9 + kk];
            g4[ttl * 145 + (kk << 4) + cv] = xT4[pos * 16 + cv];
        }
        __syncthreads();

        float4 acc = make_float4(0.f, 0.f, 0.f, 0.f);
        const float* gp = gbuf + tt * 580;
        #pragma unroll 4
        for (int r = 0; r < 576; ++r) {       // r = kk*64 + c
            float4 wv = W4[(r << 4) + og];    // conflict-free LDS.128
            float  gv = gp[r];                // 2-addr broadcast, padded banks
            acc.x = fmaf(wv.x, gv, acc.x);
            acc.y = fmaf(wv.y, gv, acc.y);
            acc.z = fmaf(wv.z, gv, acc.z);
            acc.w = fmaf(wv.w, gv, acc.w);
        }
        int t = t0 + tt;
        float4 res = ((const float4*)g_xT)[((size_t)b * HW + t) * 16 + og];
        int o0 = og << 2;
        float* outp = out + (size_t)b * 64 * HW + t;
        outp[(size_t)o0 * HW]       = fmaf(gamma0, fmaxf(acc.x + b0, 0.f), res.x);
        outp[(size_t)(o0 + 1) * HW] = fmaf(gamma0, fmaxf(acc.y + b1, 0.f), res.y);
        outp[(size_t)(o0 + 2) * HW] = fmaf(gamma0, fmaxf(acc.z + b2, 0.f), res.z);
        outp[(size_t)(o0 + 3) * HW] = fmaf(gamma0, fmaxf(acc.w + b3, 0.f), res.w);
    }
}

// ---------------- launch ----------------------------------------------------
extern "C" void kernel_launch(void* const* d_in, const int* in_sizes, int n_in,
                              void* d_out, int out_size) {
    const float* x      = (const float*)d_in[0];
    const float* qw     = (const float*)d_in[1];
    const float* qb     = (const float*)d_in[2];
    const float* kw     = (const float*)d_in[3];
    const float* kb     = (const float*)d_in[4];
    const float* gamma  = (const float*)d_in[5];
    const float* weight = (const float*)d_in[6];
    const float* bias   = (const float*)d_in[7];
    float* out = (float*)d_out;

    // 222848 B dynamic smem for k_conv (idempotent; first call is pre-capture)
    cudaFuncSetAttribute(k_conv, cudaFuncAttributeMaxDynamicSharedMemorySize, 222848);

    k_prep_w<<<144, 256>>>(weight);
    k_proj<<<128, 128>>>(x, qw, qb, kw, kb);
    k_topk<<<256, 256>>>();
    k_conv<<<128, 512, 222848>>>(bias, gamma, out);
}